// round 7
// baseline (speedup 1.0000x reference)
#include <cuda_runtime.h>
#include <math.h>

// Problem constants (fixed shapes from reference setup_inputs)
#define BB   64
#define AA   3
#define CC   11
#define HH   80
#define WW   80
#define TT   50
#define HWSZ (HH * WW)                // 6400
#define NCH  (AA * (5 + CC))          // 48
#define CPA  (5 + CC)                 // 16 channels per anchor
#define NTOT (BB * AA * HWSZ)         // 1,228,800
#define NTGT (BB * TT)                // 3200
#define EPSF 1e-7f

#define TPB   1024
#define GRID  148                     // one CTA per SM, single wave
#define OBJ_F4 (NTOT / 4)             // 307200 float4 to process
#define STRIDE1 (GRID * TPB)          // 151552
#define STRIDE2 (2 * GRID * TPB)      // 303104  (< OBJ_F4, so pass 0/1 always valid)
// pass 2 covers f4 in [303104, 307200): only first 4096 threads of early blocks

// Per-block partials [lb, lc, ssp, swm]; one STG.128 per block, no contention.
__device__ float4 g_part[GRID];
__device__ unsigned int g_counter;    // zero-init; reset by last block each replay

__device__ __forceinline__ float warp_sum(float v) {
#pragma unroll
    for (int o = 16; o > 0; o >>= 1) v += __shfl_down_sync(0xffffffffu, v, o);
    return v;
}
__device__ __forceinline__ double warp_sumd(double v) {
#pragma unroll
    for (int o = 16; o > 0; o >>= 1) v += __shfl_down_sync(0xffffffffu, v, o);
    return v;
}

__device__ __forceinline__ float sigmoidf(float x) {
    return 1.0f / (1.0f + __expf(-x));
}

// Grouped softplus over 4 values: sum(max(x,0)) + log(prod(1 + e^-|x|)).
__device__ __forceinline__ float sp4(float4 v) {
    float m = fmaxf(v.x, 0.0f) + fmaxf(v.y, 0.0f)
            + fmaxf(v.z, 0.0f) + fmaxf(v.w, 0.0f);
    float z0 = __expf(-fabsf(v.x));
    float z1 = __expf(-fabsf(v.y));
    float z2 = __expf(-fabsf(v.z));
    float z3 = __expf(-fabsf(v.w));
    float p = (1.0f + z0) * (1.0f + z1) * (1.0f + z2) * (1.0f + z3);
    return m + __logf(p);
}

// objectness plane address for float4 index f4 (4800 f4 per batch item, 1600 per anchor)
__device__ __forceinline__ const float4* obj_addr(const float* pred, int f4) {
    const int b   = f4 / 4800;
    const int rem = f4 - b * 4800;
    const int a   = rem / 1600;
    const int hw4 = rem - a * 1600;
    return reinterpret_cast<const float4*>(
        pred + (size_t)(b * NCH + a * CPA + 4) * HWSZ) + hw4;
}

// Robust scalar load: handles int32, int64 (LE low word), or float32 encoding.
__device__ __forceinline__ float load_stride(const void* p) {
    int iv = *reinterpret_cast<const int*>(p);
    if (iv > 0 && iv < 100000) return (float)iv;
    return __int_as_float(iv);
}

__global__ void __launch_bounds__(TPB, 1)
k_fused(const float* __restrict__ pred,
        const float* __restrict__ boxes,
        const int*   __restrict__ classes,
        const float* __restrict__ anchors,
        const void*  __restrict__ stride_p,
        float*       __restrict__ out) {
    const int blk = blockIdx.x;
    const int tid = threadIdx.x;

    float lb = 0.0f, lc = 0.0f, ssp = 0.0f, swm = 0.0f;

    __shared__ int   s_cell[256];        // target dedup scratch (tid < 200 used)
    __shared__ float s_red[32][4];
    __shared__ double s_d[32][4];

    // ---------------- objectness: 2 (+1 partial) float4 per thread ---------
    {
        const int f0 = blk * TPB + tid;           // < 151552, always valid
        const int f1 = f0 + STRIDE1;              // < 303104, always valid
        const int f2 = f0 + STRIDE2;              // valid iff < 307200
        const bool v2ok = (f2 < OBJ_F4);
        const float4 v0 = *obj_addr(pred, f0);
        const float4 v1 = *obj_addr(pred, f1);
        float4 v2 = make_float4(0.f, 0.f, 0.f, 0.f);
        if (v2ok) v2 = *obj_addr(pred, f2);
        ssp = sp4(v0) + sp4(v1);
        if (v2ok) ssp += sp4(v2);
    }

    // ---------------- targets: blocks 0..15, threads 0..199 ----------------
    if (blk < 16) {
        const int item_local = tid / TT;          // batch item within block
        const int t_local    = tid - item_local * TT;
        const bool active = (tid < 200);          // 4 items * 50 targets
        int my_cell = -1;
        bool valid = false;
        int b = 0, best = 0, gi_c = 0, gj_c = 0;
        float ciou = 0.0f, cls_sum = 0.0f;

        if (active) {
            b = blk * 4 + item_local;
            const int i = b * TT + t_local;       // global target index
            const float s = load_stride(stride_p);
            const float inv_s = 1.0f / s;

            const float4 bx = *reinterpret_cast<const float4*>(boxes + (size_t)i * 4);
            const float x1 = bx.x, y1 = bx.y, x2 = bx.z, y2 = bx.w;
            const float cx = (x1 + x2) * 0.5f, cy = (y1 + y2) * 0.5f;
            const float tw = x2 - x1, th = y2 - y1;

            const float gx = cx * inv_s, gy = cy * inv_s;
            const float gw = tw * inv_s, gh = th * inv_s;
            const int gi = (int)gx;   // truncation (gx >= 0)
            const int gj = (int)gy;
            valid = (gi >= 0) && (gi < WW) && (gj >= 0) && (gj < HH);
            gi_c = min(max(gi, 0), WW - 1);
            gj_c = min(max(gj, 0), HH - 1);

            // anchor argmin over penalty, first-min wins
            float best_pen = 3.402823e38f;
#pragma unroll
            for (int a = 0; a < AA; a++) {
                const float aw_ = anchors[2 * a], ah_ = anchors[2 * a + 1];
                const float rw = gw / aw_, rh = gh / ah_;
                const float pen = fmaxf(fmaxf(rw, 1.0f / rw), fmaxf(rh, 1.0f / rh));
                if (pen < best_pen) { best_pen = pen; best = a; }
            }
            const float aw = anchors[2 * best], ah = anchors[2 * best + 1];

            const size_t base = (size_t)(b * NCH + best * CPA) * HWSZ
                              + (size_t)gj_c * WW + gi_c;

            // Issue all scattered loads up front for MLP.
            float pv[4];
#pragma unroll
            for (int k = 0; k < 4; k++) pv[k] = pred[base + (size_t)k * HWSZ];
            float cv[CC];
#pragma unroll
            for (int c = 0; c < CC; c++) cv[c] = pred[base + (size_t)(5 + c) * HWSZ];
            const int cls_t = classes[i];

            const float px = sigmoidf(pv[0]) + (float)gi_c;
            const float py = sigmoidf(pv[1]) + (float)gj_c;
            const float pw = __expf(pv[2]) * aw;
            const float ph = __expf(pv[3]) * ah;

            const float px1 = (px - pw * 0.5f) * s;
            const float py1 = (py - ph * 0.5f) * s;
            const float px2 = (px + pw * 0.5f) * s;
            const float py2 = (py + ph * 0.5f) * s;

            // CIoU
            const float iw = fmaxf(fminf(px2, x2) - fmaxf(px1, x1), 0.0f);
            const float ih = fmaxf(fminf(py2, y2) - fmaxf(py1, y1), 0.0f);
            const float inter = iw * ih;
            const float pa = (px2 - px1) * (py2 - py1);
            const float ta = tw * th;
            const float uni = pa + ta - inter + EPSF;
            const float iou = inter / uni;
            const float cw = fmaxf(px2, x2) - fminf(px1, x1);
            const float chh = fmaxf(py2, y2) - fminf(py1, y1);
            const float c2 = cw * cw + chh * chh + EPSF;
            const float dx = px1 + px2 - x1 - x2;
            const float dy = py1 + py2 - y1 - y2;
            const float rho2 = (dx * dx + dy * dy) * 0.25f;
            const float k4pi2 = 4.0f / (float)(M_PI * M_PI);
            const float dat = atanf(tw / (th + EPSF))
                            - atanf((px2 - px1) / ((py2 - py1) + EPSF));
            const float v = k4pi2 * dat * dat;
            const float alpha = v / (v - iou + 1.0f + EPSF);
            ciou = 1.0f - iou + rho2 / c2 + alpha * v;

            // classification BCE vs one-hot
#pragma unroll
            for (int c = 0; c < CC; c++) {
                const float x = cv[c];
                const float tgt = (c == cls_t) ? 1.0f : 0.0f;
                cls_sum += fmaxf(x, 0.0f) + __logf(1.0f + __expf(-fabsf(x))) - x * tgt;
            }

            if (valid)
                my_cell = (b * AA + best) * HWSZ + gj_c * WW + gi_c;
        }
        if (tid < 256) s_cell[tid] = (active ? my_cell : -1);
        __syncthreads();

        if (active && valid) {
            lb = ciou;
            lc = cls_sum;
            // dedup within this batch item's 50 targets: lowest index wins the cell
            bool rep = true;
            const int b0 = item_local * TT;
            for (int j = b0; j < tid; j++)
                if (s_cell[j] == my_cell) { rep = false; break; }
            if (rep) {
                const float pobj = pred[(size_t)(b * NCH + best * CPA + 4) * HWSZ
                                        + (size_t)gj_c * WW + gi_c];
                swm = (float)(BB - b) * pobj;
            }
        }
    }

    // ---------------- block reduction -> one uncontended STG.128 -----------
    const int wid = tid >> 5, lane = tid & 31;
    float r0 = warp_sum(lb), r1 = warp_sum(lc), r2 = warp_sum(ssp), r3 = warp_sum(swm);
    if (lane == 0) {
        s_red[wid][0] = r0; s_red[wid][1] = r1;
        s_red[wid][2] = r2; s_red[wid][3] = r3;
    }
    __syncthreads();
    // warp 0 reduces the 32 warp partials (lane w holds warp w's values)
    if (wid == 0) {
        float t0 = s_red[lane][0], t1 = s_red[lane][1];
        float t2 = s_red[lane][2], t3 = s_red[lane][3];
        t0 = warp_sum(t0); t1 = warp_sum(t1); t2 = warp_sum(t2); t3 = warp_sum(t3);
        if (lane == 0) {
            g_part[blk] = make_float4(t0, t1, t2, t3);
            __threadfence();
            unsigned int done;
            asm volatile("atom.global.add.u32 %0, [%1], 1;"
                         : "=r"(done) : "l"(&g_counter) : "memory");
            s_cell[0] = (done == GRID - 1) ? 1 : 0;
        }
    }
    __syncthreads();

    // ---------------- last block: final reduction (parallel, one round) ----
    if (s_cell[0] == 1) {
        __threadfence();
        double d0 = 0.0, d1 = 0.0, d2 = 0.0, d3 = 0.0;
        if (tid < GRID) {
            const float4 p = g_part[tid];
            d0 = (double)p.x; d1 = (double)p.y;
            d2 = (double)p.z; d3 = (double)p.w;
        }
        d0 = warp_sumd(d0); d1 = warp_sumd(d1);
        d2 = warp_sumd(d2); d3 = warp_sumd(d3);
        if (lane == 0) { s_d[wid][0] = d0; s_d[wid][1] = d1;
                         s_d[wid][2] = d2; s_d[wid][3] = d3; }
        __syncthreads();
        if (tid == 0) {
            double loss_box = 0.0, loss_cls = 0.0, sp_sum = 0.0, wm = 0.0;
#pragma unroll
            for (int w = 0; w < 5; w++) {   // only warps 0..4 cover tid < 148
                loss_box += s_d[w][0]; loss_cls += s_d[w][1];
                sp_sum   += s_d[w][2]; wm       += s_d[w][3];
            }
            const double loss_obj = ((double)BB * sp_sum - wm) / (double)NTOT;
            const double num_targets = (double)NTGT;
            out[0] = (float)(5.0 * loss_box / num_targets
                           + loss_obj / (double)BB
                           + loss_cls / num_targets);
            g_counter = 0u;   // reset for next graph replay
        }
    }
}

extern "C" void kernel_launch(void* const* d_in, const int* in_sizes, int n_in,
                              void* d_out, int out_size) {
    const float* pred    = (const float*)d_in[0];
    const float* boxes   = (const float*)d_in[1];
    const int*   classes = (const int*)  d_in[2];
    const float* anchors = (const float*)d_in[3];
    const void*  stridep = (n_in > 4) ? d_in[4] : nullptr;
    float* out = (float*)d_out;
    (void)in_sizes; (void)out_size;

    k_fused<<<GRID, TPB>>>(pred, boxes, classes, anchors, stridep, out);
}

// round 8
// speedup vs baseline: 1.4332x; 1.4332x over previous
#include <cuda_runtime.h>
#include <math.h>

// Problem constants (fixed shapes from reference setup_inputs)
#define BB   64
#define AA   3
#define CC   11
#define HH   80
#define WW   80
#define TT   50
#define HWSZ (HH * WW)                // 6400
#define NCH  (AA * (5 + CC))          // 48
#define CPA  (5 + CC)                 // 16
#define NTOT (BB * AA * HWSZ)         // 1,228,800
#define NTGT (BB * TT)                // 3200
#define EPSF 1e-7f

#define TPB        320                // 10 warps
#define TGT_BLOCKS 16                 // blocks 0..15: 4 batch items * 50 targets each
#define OBJ_BLOCKS (BB * AA)          // 192: one objectness plane per block
#define GRID (TGT_BLOCKS + OBJ_BLOCKS)
#define F4_PER_PLANE 1600             // 6400 floats / 4
#define F4_PER_THREAD 5               // 320 * 5 = 1600 exactly

// Global accumulators (f32 RED targets) + completion counter.
__device__ float g_acc[4];            // [lb, lc, ssp, swm], zero-init, reset each replay
__device__ unsigned int g_counter;

__device__ __forceinline__ float warp_sum(float v) {
#pragma unroll
    for (int o = 16; o > 0; o >>= 1) v += __shfl_down_sync(0xffffffffu, v, o);
    return v;
}

__device__ __forceinline__ float sigmoidf(float x) {
    return 1.0f / (1.0f + __expf(-x));
}

// Grouped softplus over 4 values: sum(max(x,0)) + log(prod(1 + e^-|x|)).
__device__ __forceinline__ float sp4(float4 v) {
    float m = fmaxf(v.x, 0.0f) + fmaxf(v.y, 0.0f)
            + fmaxf(v.z, 0.0f) + fmaxf(v.w, 0.0f);
    float z0 = __expf(-fabsf(v.x));
    float z1 = __expf(-fabsf(v.y));
    float z2 = __expf(-fabsf(v.z));
    float z3 = __expf(-fabsf(v.w));
    float p = (1.0f + z0) * (1.0f + z1) * (1.0f + z2) * (1.0f + z3);
    return m + __logf(p);
}

// Robust scalar load: handles int32, int64 (LE low word), or float32 encoding.
__device__ __forceinline__ float load_stride(const void* p) {
    int iv = *reinterpret_cast<const int*>(p);
    if (iv > 0 && iv < 100000) return (float)iv;
    return __int_as_float(iv);
}

__global__ void __launch_bounds__(TPB)
k_fused(const float* __restrict__ pred,
        const float* __restrict__ boxes,
        const int*   __restrict__ classes,
        const float* __restrict__ anchors,
        const void*  __restrict__ stride_p,
        float*       __restrict__ out) {
    const int blk = blockIdx.x;
    const int tid = threadIdx.x;

    float lb = 0.0f, lc = 0.0f, ssp = 0.0f, swm = 0.0f;

    __shared__ int   s_cell[224];        // target dedup scratch (tid < 200 used)
    __shared__ float s_red[10][4];

    if (blk >= TGT_BLOCKS) {
        // --------- objectness plane: contiguous, division-free addressing ---
        const int plane = blk - TGT_BLOCKS;          // 0..191  (= b*3 + a)
        // base channel = plane*16 + 4  ->  weight applied via batch index later? No:
        // ssp is the UNWEIGHTED softplus sum; weighting only enters swm (targets).
        const float4* pl = reinterpret_cast<const float4*>(
            pred + (size_t)(plane * CPA + 4) * HWSZ * 1 + 0)
            ;  // placeholder, fixed below
        // NOTE: channel stride: plane p = b*AA + a ; channel index = b*NCH + a*CPA + 4
        //       = (b*3 + a)*16 + 4 = p*16 + 4. Contiguity by construction.
        pl = reinterpret_cast<const float4*>(pred) + (size_t)(plane * CPA + 4) * (HWSZ / 4);

        float4 v[F4_PER_THREAD];
#pragma unroll
        for (int k = 0; k < F4_PER_THREAD; k++)
            v[k] = pl[tid + k * TPB];
#pragma unroll
        for (int k = 0; k < F4_PER_THREAD; k++)
            ssp += sp4(v[k]);
    } else {
        // --------- targets: 4 batch items * 50 targets, threads 0..199 ------
        const int item_local = tid / TT;
        const int t_local    = tid - item_local * TT;
        const bool active = (tid < 200);
        int my_cell = -1;
        bool valid = false;
        int b = 0, best = 0, gi_c = 0, gj_c = 0;
        float ciou = 0.0f, cls_sum = 0.0f;

        if (active) {
            b = blk * 4 + item_local;
            const int i = b * TT + t_local;
            const float s = load_stride(stride_p);
            const float inv_s = 1.0f / s;

            const float4 bx = *reinterpret_cast<const float4*>(boxes + (size_t)i * 4);
            const float x1 = bx.x, y1 = bx.y, x2 = bx.z, y2 = bx.w;
            const float cx = (x1 + x2) * 0.5f, cy = (y1 + y2) * 0.5f;
            const float tw = x2 - x1, th = y2 - y1;

            const float gx = cx * inv_s, gy = cy * inv_s;
            const float gw = tw * inv_s, gh = th * inv_s;
            const int gi = (int)gx;   // truncation (gx >= 0)
            const int gj = (int)gy;
            valid = (gi >= 0) && (gi < WW) && (gj >= 0) && (gj < HH);
            gi_c = min(max(gi, 0), WW - 1);
            gj_c = min(max(gj, 0), HH - 1);

            float best_pen = 3.402823e38f;
#pragma unroll
            for (int a = 0; a < AA; a++) {
                const float aw_ = anchors[2 * a], ah_ = anchors[2 * a + 1];
                const float rw = gw / aw_, rh = gh / ah_;
                const float pen = fmaxf(fmaxf(rw, 1.0f / rw), fmaxf(rh, 1.0f / rh));
                if (pen < best_pen) { best_pen = pen; best = a; }
            }
            const float aw = anchors[2 * best], ah = anchors[2 * best + 1];

            const size_t base = (size_t)(b * NCH + best * CPA) * HWSZ
                              + (size_t)gj_c * WW + gi_c;

            float pv[4];
#pragma unroll
            for (int k = 0; k < 4; k++) pv[k] = pred[base + (size_t)k * HWSZ];
            float cv[CC];
#pragma unroll
            for (int c = 0; c < CC; c++) cv[c] = pred[base + (size_t)(5 + c) * HWSZ];
            const int cls_t = classes[i];

            const float px = sigmoidf(pv[0]) + (float)gi_c;
            const float py = sigmoidf(pv[1]) + (float)gj_c;
            const float pw = __expf(pv[2]) * aw;
            const float ph = __expf(pv[3]) * ah;

            const float px1 = (px - pw * 0.5f) * s;
            const float py1 = (py - ph * 0.5f) * s;
            const float px2 = (px + pw * 0.5f) * s;
            const float py2 = (py + ph * 0.5f) * s;

            const float iw = fmaxf(fminf(px2, x2) - fmaxf(px1, x1), 0.0f);
            const float ih = fmaxf(fminf(py2, y2) - fmaxf(py1, y1), 0.0f);
            const float inter = iw * ih;
            const float pa = (px2 - px1) * (py2 - py1);
            const float ta = tw * th;
            const float uni = pa + ta - inter + EPSF;
            const float iou = inter / uni;
            const float cw = fmaxf(px2, x2) - fminf(px1, x1);
            const float chh = fmaxf(py2, y2) - fminf(py1, y1);
            const float c2 = cw * cw + chh * chh + EPSF;
            const float dx = px1 + px2 - x1 - x2;
            const float dy = py1 + py2 - y1 - y2;
            const float rho2 = (dx * dx + dy * dy) * 0.25f;
            const float k4pi2 = 4.0f / (float)(M_PI * M_PI);
            const float dat = atanf(tw / (th + EPSF))
                            - atanf((px2 - px1) / ((py2 - py1) + EPSF));
            const float v = k4pi2 * dat * dat;
            const float alpha = v / (v - iou + 1.0f + EPSF);
            ciou = 1.0f - iou + rho2 / c2 + alpha * v;

#pragma unroll
            for (int c = 0; c < CC; c++) {
                const float x = cv[c];
                const float tgt = (c == cls_t) ? 1.0f : 0.0f;
                cls_sum += fmaxf(x, 0.0f) + __logf(1.0f + __expf(-fabsf(x))) - x * tgt;
            }

            if (valid)
                my_cell = (b * AA + best) * HWSZ + gj_c * WW + gi_c;
            s_cell[tid] = my_cell;
        }
        __syncthreads();

        if (active && valid) {
            lb = ciou;
            lc = cls_sum;
            // dedup within this batch item's 50 targets: lowest index wins
            bool rep = true;
            const int b0 = item_local * TT;
            for (int j = b0; j < tid; j++)
                if (s_cell[j] == my_cell) { rep = false; break; }
            if (rep) {
                const float pobj = pred[(size_t)(b * NCH + best * CPA + 4) * HWSZ
                                        + (size_t)gj_c * WW + gi_c];
                swm = (float)(BB - b) * pobj;
            }
        }
    }

    // --------- block reduction (10 warps) -> conditional f32 REDs ----------
    const int wid = tid >> 5, lane = tid & 31;
    float r0 = warp_sum(lb), r1 = warp_sum(lc), r2 = warp_sum(ssp), r3 = warp_sum(swm);
    if (lane == 0) {
        s_red[wid][0] = r0; s_red[wid][1] = r1;
        s_red[wid][2] = r2; s_red[wid][3] = r3;
    }
    __syncthreads();
    if (wid == 0) {
        float t0 = 0.f, t1 = 0.f, t2 = 0.f, t3 = 0.f;
        if (lane < 10) { t0 = s_red[lane][0]; t1 = s_red[lane][1];
                         t2 = s_red[lane][2]; t3 = s_red[lane][3]; }
#pragma unroll
        for (int o = 8; o > 0; o >>= 1) {
            t0 += __shfl_down_sync(0xffffffffu, t0, o);
            t1 += __shfl_down_sync(0xffffffffu, t1, o);
            t2 += __shfl_down_sync(0xffffffffu, t2, o);
            t3 += __shfl_down_sync(0xffffffffu, t3, o);
        }
        if (lane == 0) {
            if (t0 != 0.f) atomicAdd(&g_acc[0], t0);
            if (t1 != 0.f) atomicAdd(&g_acc[1], t1);
            if (t2 != 0.f) atomicAdd(&g_acc[2], t2);
            if (t3 != 0.f) atomicAdd(&g_acc[3], t3);
            __threadfence();
            const unsigned int done = atomicAdd(&g_counter, 1u);
            if (done == GRID - 1) {
                // all blocks' REDs are visible (fence-before-counter on each)
                const double loss_box = (double)g_acc[0];
                const double loss_cls = (double)g_acc[1];
                const double sp_sum   = (double)g_acc[2];
                const double wm       = (double)g_acc[3];
                const double loss_obj = ((double)BB * sp_sum - wm) / (double)NTOT;
                const double num_targets = (double)NTGT;
                out[0] = (float)(5.0 * loss_box / num_targets
                               + loss_obj / (double)BB
                               + loss_cls / num_targets);
                // reset for next graph replay
                g_acc[0] = 0.f; g_acc[1] = 0.f; g_acc[2] = 0.f; g_acc[3] = 0.f;
                g_counter = 0u;
            }
        }
    }
}

extern "C" void kernel_launch(void* const* d_in, const int* in_sizes, int n_in,
                              void* d_out, int out_size) {
    const float* pred    = (const float*)d_in[0];
    const float* boxes   = (const float*)d_in[1];
    const int*   classes = (const int*)  d_in[2];
    const float* anchors = (const float*)d_in[3];
    const void*  stridep = (n_in > 4) ? d_in[4] : nullptr;
    float* out = (float*)d_out;
    (void)in_sizes; (void)out_size;

    k_fused<<<GRID, TPB>>>(pred, boxes, classes, anchors, stridep, out);
}